// round 1
// baseline (speedup 1.0000x reference)
#include <cuda_runtime.h>
#include <math.h>

// Problem constants
constexpr int BATCH = 4;
constexpr int NTOK  = 4096;   // h*w
constexpr int CD    = 128;    // channels (C_IN == C_INNER)

// Attention tiling
constexpr int BQ = 128;       // query tile per CTA
constexpr int BK = 64;        // key tile per iteration
constexpr int PQ = BQ + 4;    // smem pitches (floats), multiples of 4 for float4
constexpr int PK = BK + 4;
constexpr int PV = CD + 4;
constexpr int PP = BQ + 4;

// Scratch (device globals: allocation-free rule)
__device__ float g_WT[3 * CD * CD];   // Wq^T, Wk^T, Wv^T as [c][o]
__device__ float g_WoT[CD * CD];      // Wo^T as [c][o]
__device__ float g_Q[BATCH * CD * NTOK];   // [b][d][tok]  (channel-major)
__device__ float g_K[BATCH * CD * NTOK];   // [b][d][tok]
__device__ float g_V[BATCH * NTOK * CD];   // [b][tok][d]  (token-major)
__device__ float g_O[BATCH * CD * NTOK];   // [b][d][tok]

// ---------------------------------------------------------------------------
// Kernel 0: transpose the four 128x128 weight matrices (tiny; keeps main GEMM
// smem loads coalesced + conflict-free).
// ---------------------------------------------------------------------------
__global__ void k_transpose_w(const float* __restrict__ Wq,
                              const float* __restrict__ Wk,
                              const float* __restrict__ Wv,
                              const float* __restrict__ Wo) {
    const float* src;
    float* dst;
    int w = blockIdx.x;
    if      (w == 0) { src = Wq; dst = g_WT;               }
    else if (w == 1) { src = Wk; dst = g_WT + CD * CD;     }
    else if (w == 2) { src = Wv; dst = g_WT + 2 * CD * CD; }
    else             { src = Wo; dst = g_WoT;              }
    for (int idx = threadIdx.x; idx < CD * CD; idx += blockDim.x) {
        int o = idx / CD, c = idx % CD;
        dst[c * CD + o] = src[idx];  // read coalesced, 64KB each: negligible
    }
}

// ---------------------------------------------------------------------------
// Kernel 1: fused QKV 1x1 convs. One CTA = one batch x 128-token tile, all 128
// output channels, looping the three weights while reusing the X tile in smem.
// Q,K stored channel-major; V stored token-major.
// smem: Ws[128][132] + Xs[128][132]  (dynamic, 135168 B)
// ---------------------------------------------------------------------------
constexpr int SM_GEMM = 2 * CD * (CD + 4) * 4;

__global__ __launch_bounds__(256, 1)
void k_qkv(const float* __restrict__ x,
           const float* __restrict__ bq,
           const float* __restrict__ bk,
           const float* __restrict__ bv) {
    extern __shared__ float sm[];
    float* Ws = sm;                  // [c][o], pitch CD+4
    float* Xs = sm + CD * (CD + 4);  // [c][p], pitch CD+4
    constexpr int PW = CD + 4;

    const int b  = blockIdx.y;
    const int p0 = blockIdx.x * 128;
    const int tid = threadIdx.x;
    const int ty = tid >> 4, tx = tid & 15;

    // Load X tile [128 c][128 p] (coalesced float4)
    for (int idx = tid; idx < CD * 32; idx += 256) {
        int c = idx >> 5, c4 = (idx & 31) * 4;
        *(float4*)(Xs + c * PW + c4) =
            *(const float4*)(x + ((size_t)(b * CD + c)) * NTOK + p0 + c4);
    }

    for (int w = 0; w < 3; w++) {
        __syncthreads();
        for (int idx = tid; idx < CD * 32; idx += 256) {
            int c = idx >> 5, c4 = (idx & 31) * 4;
            *(float4*)(Ws + c * PW + c4) =
                *(const float4*)(g_WT + w * CD * CD + c * CD + c4);
        }
        __syncthreads();

        float acc[8][8];
#pragma unroll
        for (int i = 0; i < 8; i++)
#pragma unroll
            for (int j = 0; j < 8; j++) acc[i][j] = 0.f;

#pragma unroll 4
        for (int c = 0; c < CD; c++) {
            float4 w0 = *(float4*)(Ws + c * PW + ty * 8);
            float4 w1 = *(float4*)(Ws + c * PW + ty * 8 + 4);
            float4 x0 = *(float4*)(Xs + c * PW + tx * 8);
            float4 x1 = *(float4*)(Xs + c * PW + tx * 8 + 4);
            float wr[8] = {w0.x, w0.y, w0.z, w0.w, w1.x, w1.y, w1.z, w1.w};
            float xr[8] = {x0.x, x0.y, x0.z, x0.w, x1.x, x1.y, x1.z, x1.w};
#pragma unroll
            for (int i = 0; i < 8; i++)
#pragma unroll
                for (int j = 0; j < 8; j++) acc[i][j] += wr[i] * xr[j];
        }

        const float* bias = (w == 0) ? bq : (w == 1) ? bk : bv;
#pragma unroll
        for (int i = 0; i < 8; i++) {
            float bb = bias[ty * 8 + i];
#pragma unroll
            for (int j = 0; j < 8; j++) acc[i][j] += bb;
        }

        if (w < 2) {  // channel-major store
            float* dst = (w == 0) ? g_Q : g_K;
#pragma unroll
            for (int i = 0; i < 8; i++) {
                float* r = dst + ((size_t)(b * CD + ty * 8 + i)) * NTOK + p0 + tx * 8;
                *(float4*)(r)     = make_float4(acc[i][0], acc[i][1], acc[i][2], acc[i][3]);
                *(float4*)(r + 4) = make_float4(acc[i][4], acc[i][5], acc[i][6], acc[i][7]);
            }
        } else {      // token-major store for V
#pragma unroll
            for (int j = 0; j < 8; j++) {
                float* r = g_V + ((size_t)(b * NTOK + p0 + tx * 8 + j)) * CD + ty * 8;
                *(float4*)(r)     = make_float4(acc[0][j], acc[1][j], acc[2][j], acc[3][j]);
                *(float4*)(r + 4) = make_float4(acc[4][j], acc[5][j], acc[6][j], acc[7][j]);
            }
        }
    }
}

// ---------------------------------------------------------------------------
// Kernel 2: flash attention, fp32. CTA = one batch x 128-query tile; iterates
// 64-key tiles with online softmax. 256 threads = 16x16; per-thread microtiles:
// S: 4k x 8q, O: 8d x 8q.
// smem: Qs[128d][132] + Ks[128d][68] + Vs[64k][132] + Ps[64k][132] = 169984 B
// ---------------------------------------------------------------------------
constexpr int SM_ATTN = (CD * PQ + CD * PK + BK * PV + BK * PP) * 4;

__global__ __launch_bounds__(256, 1)
void k_attn() {
    extern __shared__ float sm[];
    float* Qs = sm;                 // [d][q]
    float* Ks = Qs + CD * PQ;       // [d][k]
    float* Vs = Ks + CD * PK;       // [k][d]
    float* Ps = Vs + BK * PV;       // [k][q]

    const int b  = blockIdx.y;
    const int q0 = blockIdx.x * BQ;
    const int tid = threadIdx.x;
    const int ty = tid >> 4, tx = tid & 15;

    // Load Q tile [128 d][128 q] once (native channel-major layout: no transpose)
    for (int idx = tid; idx < CD * (BQ / 4); idx += 256) {
        int d = idx >> 5, c4 = (idx & 31) * 4;
        *(float4*)(Qs + d * PQ + c4) =
            *(const float4*)(g_Q + ((size_t)(b * CD + d)) * NTOK + q0 + c4);
    }

    float m[8], l[8], o_acc[8][8];  // o_acc[d][q]
#pragma unroll
    for (int i = 0; i < 8; i++) {
        m[i] = -INFINITY; l[i] = 0.f;
#pragma unroll
        for (int j = 0; j < 8; j++) o_acc[j][i] = 0.f;
    }

    for (int kt = 0; kt < NTOK / BK; kt++) {
        const int k0 = kt * BK;
        __syncthreads();  // previous O-GEMM done reading Vs/Ps
        // K tile [128 d][64 k]
        for (int idx = tid; idx < CD * (BK / 4); idx += 256) {
            int d = idx >> 4, c4 = (idx & 15) * 4;
            *(float4*)(Ks + d * PK + c4) =
                *(const float4*)(g_K + ((size_t)(b * CD + d)) * NTOK + k0 + c4);
        }
        // V tile [64 k][128 d]
        for (int idx = tid; idx < BK * (CD / 4); idx += 256) {
            int k = idx >> 5, c4 = (idx & 31) * 4;
            *(float4*)(Vs + k * PV + c4) =
                *(const float4*)(g_V + ((size_t)(b * NTOK + k0 + k)) * CD + c4);
        }
        __syncthreads();

        // S = Q^T K  -> s[j(k)][i(q)]
        float s[4][8];
#pragma unroll
        for (int j = 0; j < 4; j++)
#pragma unroll
            for (int i = 0; i < 8; i++) s[j][i] = 0.f;

#pragma unroll 4
        for (int kk = 0; kk < CD; kk++) {
            float4 a0 = *(float4*)(Qs + kk * PQ + ty * 8);
            float4 a1 = *(float4*)(Qs + kk * PQ + ty * 8 + 4);
            float4 b4 = *(float4*)(Ks + kk * PK + tx * 4);
            float ar[8] = {a0.x, a0.y, a0.z, a0.w, a1.x, a1.y, a1.z, a1.w};
            float br[4] = {b4.x, b4.y, b4.z, b4.w};
#pragma unroll
            for (int j = 0; j < 4; j++)
#pragma unroll
                for (int i = 0; i < 8; i++) s[j][i] += br[j] * ar[i];
        }

        // Online softmax per q-row (row spread over 16 lanes with same ty)
#pragma unroll
        for (int i = 0; i < 8; i++) {
            float mx = fmaxf(fmaxf(s[0][i], s[1][i]), fmaxf(s[2][i], s[3][i]));
#pragma unroll
            for (int off = 8; off >= 1; off >>= 1)
                mx = fmaxf(mx, __shfl_xor_sync(0xffffffffu, mx, off, 16));
            float nm = fmaxf(m[i], mx);
            float sc = __expf(m[i] - nm);
            m[i] = nm;
            float rs = 0.f;
#pragma unroll
            for (int j = 0; j < 4; j++) { s[j][i] = __expf(s[j][i] - nm); rs += s[j][i]; }
#pragma unroll
            for (int off = 8; off >= 1; off >>= 1)
                rs += __shfl_xor_sync(0xffffffffu, rs, off, 16);
            l[i] = l[i] * sc + rs;
#pragma unroll
            for (int j = 0; j < 8; j++) o_acc[j][i] *= sc;
        }

        // Stage P into smem as [k][q]
#pragma unroll
        for (int j = 0; j < 4; j++) {
            float* r = Ps + (tx * 4 + j) * PP + ty * 8;
            *(float4*)(r)     = make_float4(s[j][0], s[j][1], s[j][2], s[j][3]);
            *(float4*)(r + 4) = make_float4(s[j][4], s[j][5], s[j][6], s[j][7]);
        }
        __syncthreads();

        // O += P^T V   (inner dim = k)
#pragma unroll 4
        for (int kk = 0; kk < BK; kk++) {
            float4 p0 = *(float4*)(Ps + kk * PP + ty * 8);
            float4 p1 = *(float4*)(Ps + kk * PP + ty * 8 + 4);
            float4 v0 = *(float4*)(Vs + kk * PV + tx * 8);
            float4 v1 = *(float4*)(Vs + kk * PV + tx * 8 + 4);
            float pr[8] = {p0.x, p0.y, p0.z, p0.w, p1.x, p1.y, p1.z, p1.w};
            float vr[8] = {v0.x, v0.y, v0.z, v0.w, v1.x, v1.y, v1.z, v1.w};
#pragma unroll
            for (int j = 0; j < 8; j++)
#pragma unroll
                for (int i = 0; i < 8; i++) o_acc[j][i] += vr[j] * pr[i];
        }
    }

    // Normalize and store channel-major (native for the Wo GEMM)
#pragma unroll
    for (int i = 0; i < 8; i++) {
        float inv = 1.0f / l[i];
#pragma unroll
        for (int j = 0; j < 8; j++) o_acc[j][i] *= inv;
    }
#pragma unroll
    for (int j = 0; j < 8; j++) {
        float* r = g_O + ((size_t)(b * CD + tx * 8 + j)) * NTOK + q0 + ty * 8;
        *(float4*)(r)     = make_float4(o_acc[j][0], o_acc[j][1], o_acc[j][2], o_acc[j][3]);
        *(float4*)(r + 4) = make_float4(o_acc[j][4], o_acc[j][5], o_acc[j][6], o_acc[j][7]);
    }
}

// ---------------------------------------------------------------------------
// Kernel 3: out = Wo @ O + bo + x  (residual fused)
// ---------------------------------------------------------------------------
__global__ __launch_bounds__(256, 1)
void k_out(const float* __restrict__ x,
           const float* __restrict__ bo,
           float* __restrict__ out) {
    extern __shared__ float sm[];
    float* Ws = sm;                  // [c][o]
    float* Os = sm + CD * (CD + 4);  // [c][p]
    constexpr int PW = CD + 4;

    const int b  = blockIdx.y;
    const int p0 = blockIdx.x * 128;
    const int tid = threadIdx.x;
    const int ty = tid >> 4, tx = tid & 15;

    for (int idx = tid; idx < CD * 32; idx += 256) {
        int c = idx >> 5, c4 = (idx & 31) * 4;
        *(float4*)(Ws + c * PW + c4) = *(const float4*)(g_WoT + c * CD + c4);
        *(float4*)(Os + c * PW + c4) =
            *(const float4*)(g_O + ((size_t)(b * CD + c)) * NTOK + p0 + c4);
    }
    __syncthreads();

    float acc[8][8];
#pragma unroll
    for (int i = 0; i < 8; i++)
#pragma unroll
        for (int j = 0; j < 8; j++) acc[i][j] = 0.f;

#pragma unroll 4
    for (int c = 0; c < CD; c++) {
        float4 w0 = *(float4*)(Ws + c * PW + ty * 8);
        float4 w1 = *(float4*)(Ws + c * PW + ty * 8 + 4);
        float4 x0 = *(float4*)(Os + c * PW + tx * 8);
        float4 x1 = *(float4*)(Os + c * PW + tx * 8 + 4);
        float wr[8] = {w0.x, w0.y, w0.z, w0.w, w1.x, w1.y, w1.z, w1.w};
        float xr[8] = {x0.x, x0.y, x0.z, x0.w, x1.x, x1.y, x1.z, x1.w};
#pragma unroll
        for (int i = 0; i < 8; i++)
#pragma unroll
            for (int j = 0; j < 8; j++) acc[i][j] += wr[i] * xr[j];
    }

#pragma unroll
    for (int i = 0; i < 8; i++) {
        int o = ty * 8 + i;
        float bb = bo[o];
        const float* xr = x + ((size_t)(b * CD + o)) * NTOK + p0 + tx * 8;
        float4 xa = *(const float4*)(xr);
        float4 xb = *(const float4*)(xr + 4);
        float* r = out + ((size_t)(b * CD + o)) * NTOK + p0 + tx * 8;
        *(float4*)(r) = make_float4(acc[i][0] + bb + xa.x, acc[i][1] + bb + xa.y,
                                    acc[i][2] + bb + xa.z, acc[i][3] + bb + xa.w);
        *(float4*)(r + 4) = make_float4(acc[i][4] + bb + xb.x, acc[i][5] + bb + xb.y,
                                        acc[i][6] + bb + xb.z, acc[i][7] + bb + xb.w);
    }
}

// ---------------------------------------------------------------------------
extern "C" void kernel_launch(void* const* d_in, const int* in_sizes, int n_in,
                              void* d_out, int out_size) {
    const float* x  = (const float*)d_in[0];
    const float* Wq = (const float*)d_in[1];
    const float* bq = (const float*)d_in[2];
    const float* Wk = (const float*)d_in[3];
    const float* bk = (const float*)d_in[4];
    const float* Wv = (const float*)d_in[5];
    const float* bv = (const float*)d_in[6];
    const float* Wo = (const float*)d_in[7];
    const float* bo = (const float*)d_in[8];
    float* out = (float*)d_out;

    // Idempotent, called every launch (no static guards).
    cudaFuncSetAttribute(k_qkv,  cudaFuncAttributeMaxDynamicSharedMemorySize, SM_GEMM);
    cudaFuncSetAttribute(k_attn, cudaFuncAttributeMaxDynamicSharedMemorySize, SM_ATTN);
    cudaFuncSetAttribute(k_out,  cudaFuncAttributeMaxDynamicSharedMemorySize, SM_GEMM);

    k_transpose_w<<<4, 256>>>(Wq, Wk, Wv, Wo);
    k_qkv<<<dim3(NTOK / 128, BATCH), 256, SM_GEMM>>>(x, bq, bk, bv);
    k_attn<<<dim3(NTOK / BQ, BATCH), 256, SM_ATTN>>>();
    k_out<<<dim3(NTOK / 128, BATCH), 256, SM_GEMM>>>(x, bo, out);
}

// round 2
// speedup vs baseline: 1.0022x; 1.0022x over previous
#include <cuda_runtime.h>
#include <math.h>

// Problem constants
constexpr int BATCH = 4;
constexpr int NTOK  = 4096;   // h*w
constexpr int CD    = 128;    // channels (C_IN == C_INNER)

// Attention tiling
constexpr int BQ = 128;       // query tile per CTA
constexpr int BK = 64;        // key tile per iteration
constexpr int PQ = BQ + 4;    // smem pitches (floats), multiples of 4 for float4
constexpr int PK = BK + 4;
constexpr int PV = CD + 4;
constexpr int PP = BQ + 4;

// Scratch (device globals: allocation-free rule)
__device__ float g_WT[3 * CD * CD];   // Wq^T, Wk^T, Wv^T as [c][o]
__device__ float g_WoT[CD * CD];      // Wo^T as [c][o]
__device__ float g_Q[BATCH * CD * NTOK];   // [b][d][tok]  (channel-major)
__device__ float g_K[BATCH * CD * NTOK];   // [b][d][tok]
__device__ float g_V[BATCH * NTOK * CD];   // [b][tok][d]  (token-major)
__device__ float g_O[BATCH * CD * NTOK];   // [b][d][tok]

// ---------------------------------------------------------------------------
// Kernel 0: transpose the four 128x128 weight matrices (tiny; keeps main GEMM
// smem loads coalesced + conflict-free).
// ---------------------------------------------------------------------------
__global__ void k_transpose_w(const float* __restrict__ Wq,
                              const float* __restrict__ Wk,
                              const float* __restrict__ Wv,
                              const float* __restrict__ Wo) {
    const float* src;
    float* dst;
    int w = blockIdx.x;
    if      (w == 0) { src = Wq; dst = g_WT;               }
    else if (w == 1) { src = Wk; dst = g_WT + CD * CD;     }
    else if (w == 2) { src = Wv; dst = g_WT + 2 * CD * CD; }
    else             { src = Wo; dst = g_WoT;              }
    for (int idx = threadIdx.x; idx < CD * CD; idx += blockDim.x) {
        int o = idx / CD, c = idx % CD;
        dst[c * CD + o] = src[idx];  // read coalesced, 64KB each: negligible
    }
}

// ---------------------------------------------------------------------------
// Kernel 1: fused QKV 1x1 convs. One CTA = one batch x 128-token tile, all 128
// output channels, looping the three weights while reusing the X tile in smem.
// Q,K stored channel-major; V stored token-major.
// smem: Ws[128][132] + Xs[128][132]  (dynamic, 135168 B)
// ---------------------------------------------------------------------------
constexpr int SM_GEMM = 2 * CD * (CD + 4) * 4;

__global__ __launch_bounds__(256, 1)
void k_qkv(const float* __restrict__ x,
           const float* __restrict__ bq,
           const float* __restrict__ bk,
           const float* __restrict__ bv) {
    extern __shared__ float sm[];
    float* Ws = sm;                  // [c][o], pitch CD+4
    float* Xs = sm + CD * (CD + 4);  // [c][p], pitch CD+4
    constexpr int PW = CD + 4;

    const int b  = blockIdx.y;
    const int p0 = blockIdx.x * 128;
    const int tid = threadIdx.x;
    const int ty = tid >> 4, tx = tid & 15;

    // Load X tile [128 c][128 p] (coalesced float4)
    for (int idx = tid; idx < CD * 32; idx += 256) {
        int c = idx >> 5, c4 = (idx & 31) * 4;
        *(float4*)(Xs + c * PW + c4) =
            *(const float4*)(x + ((size_t)(b * CD + c)) * NTOK + p0 + c4);
    }

    for (int w = 0; w < 3; w++) {
        __syncthreads();
        for (int idx = tid; idx < CD * 32; idx += 256) {
            int c = idx >> 5, c4 = (idx & 31) * 4;
            *(float4*)(Ws + c * PW + c4) =
                *(const float4*)(g_WT + w * CD * CD + c * CD + c4);
        }
        __syncthreads();

        float acc[8][8];
#pragma unroll
        for (int i = 0; i < 8; i++)
#pragma unroll
            for (int j = 0; j < 8; j++) acc[i][j] = 0.f;

#pragma unroll 4
        for (int c = 0; c < CD; c++) {
            float4 w0 = *(float4*)(Ws + c * PW + ty * 8);
            float4 w1 = *(float4*)(Ws + c * PW + ty * 8 + 4);
            float4 x0 = *(float4*)(Xs + c * PW + tx * 8);
            float4 x1 = *(float4*)(Xs + c * PW + tx * 8 + 4);
            float wr[8] = {w0.x, w0.y, w0.z, w0.w, w1.x, w1.y, w1.z, w1.w};
            float xr[8] = {x0.x, x0.y, x0.z, x0.w, x1.x, x1.y, x1.z, x1.w};
#pragma unroll
            for (int i = 0; i < 8; i++)
#pragma unroll
                for (int j = 0; j < 8; j++) acc[i][j] += wr[i] * xr[j];
        }

        const float* bias = (w == 0) ? bq : (w == 1) ? bk : bv;
#pragma unroll
        for (int i = 0; i < 8; i++) {
            float bb = bias[ty * 8 + i];
#pragma unroll
            for (int j = 0; j < 8; j++) acc[i][j] += bb;
        }

        if (w < 2) {  // channel-major store
            float* dst = (w == 0) ? g_Q : g_K;
#pragma unroll
            for (int i = 0; i < 8; i++) {
                float* r = dst + ((size_t)(b * CD + ty * 8 + i)) * NTOK + p0 + tx * 8;
                *(float4*)(r)     = make_float4(acc[i][0], acc[i][1], acc[i][2], acc[i][3]);
                *(float4*)(r + 4) = make_float4(acc[i][4], acc[i][5], acc[i][6], acc[i][7]);
            }
        } else {      // token-major store for V
#pragma unroll
            for (int j = 0; j < 8; j++) {
                float* r = g_V + ((size_t)(b * NTOK + p0 + tx * 8 + j)) * CD + ty * 8;
                *(float4*)(r)     = make_float4(acc[0][j], acc[1][j], acc[2][j], acc[3][j]);
                *(float4*)(r + 4) = make_float4(acc[4][j], acc[5][j], acc[6][j], acc[7][j]);
            }
        }
    }
}

// ---------------------------------------------------------------------------
// Kernel 2: flash attention, fp32. CTA = one batch x 128-query tile; iterates
// 64-key tiles with online softmax. 256 threads = 16x16; per-thread microtiles:
// S: 4k x 8q, O: 8d x 8q.
// smem: Qs[128d][132] + Ks[128d][68] + Vs[64k][132] + Ps[64k][132] = 169984 B
// ---------------------------------------------------------------------------
constexpr int SM_ATTN = (CD * PQ + CD * PK + BK * PV + BK * PP) * 4;

__global__ __launch_bounds__(256, 1)
void k_attn() {
    extern __shared__ float sm[];
    float* Qs = sm;                 // [d][q]
    float* Ks = Qs + CD * PQ;       // [d][k]
    float* Vs = Ks + CD * PK;       // [k][d]
    float* Ps = Vs + BK * PV;       // [k][q]

    const int b  = blockIdx.y;
    const int q0 = blockIdx.x * BQ;
    const int tid = threadIdx.x;
    const int ty = tid >> 4, tx = tid & 15;

    // Load Q tile [128 d][128 q] once (native channel-major layout: no transpose)
    for (int idx = tid; idx < CD * (BQ / 4); idx += 256) {
        int d = idx >> 5, c4 = (idx & 31) * 4;
        *(float4*)(Qs + d * PQ + c4) =
            *(const float4*)(g_Q + ((size_t)(b * CD + d)) * NTOK + q0 + c4);
    }

    float m[8], l[8], o_acc[8][8];  // o_acc[d][q]
#pragma unroll
    for (int i = 0; i < 8; i++) {
        m[i] = -INFINITY; l[i] = 0.f;
#pragma unroll
        for (int j = 0; j < 8; j++) o_acc[j][i] = 0.f;
    }

    for (int kt = 0; kt < NTOK / BK; kt++) {
        const int k0 = kt * BK;
        __syncthreads();  // previous O-GEMM done reading Vs/Ps
        // K tile [128 d][64 k]
        for (int idx = tid; idx < CD * (BK / 4); idx += 256) {
            int d = idx >> 4, c4 = (idx & 15) * 4;
            *(float4*)(Ks + d * PK + c4) =
                *(const float4*)(g_K + ((size_t)(b * CD + d)) * NTOK + k0 + c4);
        }
        // V tile [64 k][128 d]
        for (int idx = tid; idx < BK * (CD / 4); idx += 256) {
            int k = idx >> 5, c4 = (idx & 31) * 4;
            *(float4*)(Vs + k * PV + c4) =
                *(const float4*)(g_V + ((size_t)(b * NTOK + k0 + k)) * CD + c4);
        }
        __syncthreads();

        // S = Q^T K  -> s[j(k)][i(q)]
        float s[4][8];
#pragma unroll
        for (int j = 0; j < 4; j++)
#pragma unroll
            for (int i = 0; i < 8; i++) s[j][i] = 0.f;

#pragma unroll 4
        for (int kk = 0; kk < CD; kk++) {
            float4 a0 = *(float4*)(Qs + kk * PQ + ty * 8);
            float4 a1 = *(float4*)(Qs + kk * PQ + ty * 8 + 4);
            float4 b4 = *(float4*)(Ks + kk * PK + tx * 4);
            float ar[8] = {a0.x, a0.y, a0.z, a0.w, a1.x, a1.y, a1.z, a1.w};
            float br[4] = {b4.x, b4.y, b4.z, b4.w};
#pragma unroll
            for (int j = 0; j < 4; j++)
#pragma unroll
                for (int i = 0; i < 8; i++) s[j][i] += br[j] * ar[i];
        }

        // Online softmax per q-row (row spread over 16 lanes with same ty)
#pragma unroll
        for (int i = 0; i < 8; i++) {
            float mx = fmaxf(fmaxf(s[0][i], s[1][i]), fmaxf(s[2][i], s[3][i]));
#pragma unroll
            for (int off = 8; off >= 1; off >>= 1)
                mx = fmaxf(mx, __shfl_xor_sync(0xffffffffu, mx, off, 16));
            float nm = fmaxf(m[i], mx);
            float sc = __expf(m[i] - nm);
            m[i] = nm;
            float rs = 0.f;
#pragma unroll
            for (int j = 0; j < 4; j++) { s[j][i] = __expf(s[j][i] - nm); rs += s[j][i]; }
#pragma unroll
            for (int off = 8; off >= 1; off >>= 1)
                rs += __shfl_xor_sync(0xffffffffu, rs, off, 16);
            l[i] = l[i] * sc + rs;
#pragma unroll
            for (int j = 0; j < 8; j++) o_acc[j][i] *= sc;
        }

        // Stage P into smem as [k][q]
#pragma unroll
        for (int j = 0; j < 4; j++) {
            float* r = Ps + (tx * 4 + j) * PP + ty * 8;
            *(float4*)(r)     = make_float4(s[j][0], s[j][1], s[j][2], s[j][3]);
            *(float4*)(r + 4) = make_float4(s[j][4], s[j][5], s[j][6], s[j][7]);
        }
        __syncthreads();

        // O += P^T V   (inner dim = k)
#pragma unroll 4
        for (int kk = 0; kk < BK; kk++) {
            float4 p0 = *(float4*)(Ps + kk * PP + ty * 8);
            float4 p1 = *(float4*)(Ps + kk * PP + ty * 8 + 4);
            float4 v0 = *(float4*)(Vs + kk * PV + tx * 8);
            float4 v1 = *(float4*)(Vs + kk * PV + tx * 8 + 4);
            float pr[8] = {p0.x, p0.y, p0.z, p0.w, p1.x, p1.y, p1.z, p1.w};
            float vr[8] = {v0.x, v0.y, v0.z, v0.w, v1.x, v1.y, v1.z, v1.w};
#pragma unroll
            for (int j = 0; j < 8; j++)
#pragma unroll
                for (int i = 0; i < 8; i++) o_acc[j][i] += vr[j] * pr[i];
        }
    }

    // Normalize and store channel-major (native for the Wo GEMM)
#pragma unroll
    for (int i = 0; i < 8; i++) {
        float inv = 1.0f / l[i];
#pragma unroll
        for (int j = 0; j < 8; j++) o_acc[j][i] *= inv;
    }
#pragma unroll
    for (int j = 0; j < 8; j++) {
        float* r = g_O + ((size_t)(b * CD + tx * 8 + j)) * NTOK + q0 + ty * 8;
        *(float4*)(r)     = make_float4(o_acc[j][0], o_acc[j][1], o_acc[j][2], o_acc[j][3]);
        *(float4*)(r + 4) = make_float4(o_acc[j][4], o_acc[j][5], o_acc[j][6], o_acc[j][7]);
    }
}

// ---------------------------------------------------------------------------
// Kernel 3: out = Wo @ O + bo + x  (residual fused)
// ---------------------------------------------------------------------------
__global__ __launch_bounds__(256, 1)
void k_out(const float* __restrict__ x,
           const float* __restrict__ bo,
           float* __restrict__ out) {
    extern __shared__ float sm[];
    float* Ws = sm;                  // [c][o]
    float* Os = sm + CD * (CD + 4);  // [c][p]
    constexpr int PW = CD + 4;

    const int b  = blockIdx.y;
    const int p0 = blockIdx.x * 128;
    const int tid = threadIdx.x;
    const int ty = tid >> 4, tx = tid & 15;

    for (int idx = tid; idx < CD * 32; idx += 256) {
        int c = idx >> 5, c4 = (idx & 31) * 4;
        *(float4*)(Ws + c * PW + c4) = *(const float4*)(g_WoT + c * CD + c4);
        *(float4*)(Os + c * PW + c4) =
            *(const float4*)(g_O + ((size_t)(b * CD + c)) * NTOK + p0 + c4);
    }
    __syncthreads();

    float acc[8][8];
#pragma unroll
    for (int i = 0; i < 8; i++)
#pragma unroll
        for (int j = 0; j < 8; j++) acc[i][j] = 0.f;

#pragma unroll 4
    for (int c = 0; c < CD; c++) {
        float4 w0 = *(float4*)(Ws + c * PW + ty * 8);
        float4 w1 = *(float4*)(Ws + c * PW + ty * 8 + 4);
        float4 x0 = *(float4*)(Os + c * PW + tx * 8);
        float4 x1 = *(float4*)(Os + c * PW + tx * 8 + 4);
        float wr[8] = {w0.x, w0.y, w0.z, w0.w, w1.x, w1.y, w1.z, w1.w};
        float xr[8] = {x0.x, x0.y, x0.z, x0.w, x1.x, x1.y, x1.z, x1.w};
#pragma unroll
        for (int i = 0; i < 8; i++)
#pragma unroll
            for (int j = 0; j < 8; j++) acc[i][j] += wr[i] * xr[j];
    }

#pragma unroll
    for (int i = 0; i < 8; i++) {
        int o = ty * 8 + i;
        float bb = bo[o];
        const float* xr = x + ((size_t)(b * CD + o)) * NTOK + p0 + tx * 8;
        float4 xa = *(const float4*)(xr);
        float4 xb = *(const float4*)(xr + 4);
        float* r = out + ((size_t)(b * CD + o)) * NTOK + p0 + tx * 8;
        *(float4*)(r) = make_float4(acc[i][0] + bb + xa.x, acc[i][1] + bb + xa.y,
                                    acc[i][2] + bb + xa.z, acc[i][3] + bb + xa.w);
        *(float4*)(r + 4) = make_float4(acc[i][4] + bb + xb.x, acc[i][5] + bb + xb.y,
                                        acc[i][6] + bb + xb.z, acc[i][7] + bb + xb.w);
    }
}

// ---------------------------------------------------------------------------
extern "C" void kernel_launch(void* const* d_in, const int* in_sizes, int n_in,
                              void* d_out, int out_size) {
    const float* x  = (const float*)d_in[0];
    const float* Wq = (const float*)d_in[1];
    const float* bq = (const float*)d_in[2];
    const float* Wk = (const float*)d_in[3];
    const float* bk = (const float*)d_in[4];
    const float* Wv = (const float*)d_in[5];
    const float* bv = (const float*)d_in[6];
    const float* Wo = (const float*)d_in[7];
    const float* bo = (const float*)d_in[8];
    float* out = (float*)d_out;

    // Idempotent, called every launch (no static guards).
    cudaFuncSetAttribute(k_qkv,  cudaFuncAttributeMaxDynamicSharedMemorySize, SM_GEMM);
    cudaFuncSetAttribute(k_attn, cudaFuncAttributeMaxDynamicSharedMemorySize, SM_ATTN);
    cudaFuncSetAttribute(k_out,  cudaFuncAttributeMaxDynamicSharedMemorySize, SM_GEMM);

    k_transpose_w<<<4, 256>>>(Wq, Wk, Wv, Wo);
    k_qkv<<<dim3(NTOK / 128, BATCH), 256, SM_GEMM>>>(x, bq, bk, bv);
    k_attn<<<dim3(NTOK / BQ, BATCH), 256, SM_ATTN>>>();
    k_out<<<dim3(NTOK / 128, BATCH), 256, SM_GEMM>>>(x, bo, out);
}